// round 1
// baseline (speedup 1.0000x reference)
#include <cuda_runtime.h>
#include <math.h>

#define T_    8
#define H_    28
#define W_    28
#define SP_   6272
#define NTOK  6273
#define DIM_  192
#define HD_   96
#define BROW  68
#define SCALE_ 0.1020620726159658f   // 96^-0.5
#define SV_STRIDE 100

// Scratch (static device memory — no allocations)
__device__ float g_raw [6 * NTOK * HD_];   // [which*2+head][tok][c]  pre-pool q,k,v
__device__ float g_pool[6 * NTOK * HD_];   // pooled+LN q,k,v
__device__ float g_bias[2 * NTOK * BROW];  // per (head, qtok): [0..7]=Bt [8..35]=Bh [36..63]=Bw [64..67]=0
__device__ float g_att [NTOK * DIM_];      // attention output (heads concatenated) + residual

// ---------------------------------------------------------------------------
// Tiled SGEMM: C[M x N] = A[M x 192] @ Bm[N x 192]^T + bias
// mode 0: scatter into g_raw (qkv).  mode 1: A := g_att, write out row-major.
// ---------------------------------------------------------------------------
__global__ __launch_bounds__(256) void gemm_kernel(
    const float* __restrict__ A, const float* __restrict__ Bm,
    const float* __restrict__ bias, float* __restrict__ out,
    int M, int N, int mode)
{
    __shared__ float sA[16][64];
    __shared__ float sB[16][64];
    const int K = 192;
    const float* Ap = (mode == 1) ? g_att : A;

    int tid = threadIdx.x;
    int tx = tid & 15, ty = tid >> 4;
    int m0 = blockIdx.x * 64, n0 = blockIdx.y * 64;
    int lr = tid >> 2;       // 0..63
    int lc = tid & 3;        // 0..3

    float acc[4][4] = {};

    for (int k0 = 0; k0 < K; k0 += 16) {
        {
            int row = m0 + lr;
            float4 v = make_float4(0.f, 0.f, 0.f, 0.f);
            if (row < M) v = *(const float4*)&Ap[row * K + k0 + lc * 4];
            sA[lc*4+0][lr] = v.x; sA[lc*4+1][lr] = v.y;
            sA[lc*4+2][lr] = v.z; sA[lc*4+3][lr] = v.w;
        }
        {
            int row = n0 + lr;
            float4 v = make_float4(0.f, 0.f, 0.f, 0.f);
            if (row < N) v = *(const float4*)&Bm[row * K + k0 + lc * 4];
            sB[lc*4+0][lr] = v.x; sB[lc*4+1][lr] = v.y;
            sB[lc*4+2][lr] = v.z; sB[lc*4+3][lr] = v.w;
        }
        __syncthreads();
        #pragma unroll
        for (int kk = 0; kk < 16; kk++) {
            float4 a = *(float4*)&sA[kk][ty * 4];
            float4 b = *(float4*)&sB[kk][tx * 4];
            acc[0][0] += a.x*b.x; acc[0][1] += a.x*b.y; acc[0][2] += a.x*b.z; acc[0][3] += a.x*b.w;
            acc[1][0] += a.y*b.x; acc[1][1] += a.y*b.y; acc[1][2] += a.y*b.z; acc[1][3] += a.y*b.w;
            acc[2][0] += a.z*b.x; acc[2][1] += a.z*b.y; acc[2][2] += a.z*b.z; acc[2][3] += a.z*b.w;
            acc[3][0] += a.w*b.x; acc[3][1] += a.w*b.y; acc[3][2] += a.w*b.z; acc[3][3] += a.w*b.w;
        }
        __syncthreads();
    }

    #pragma unroll
    for (int qi = 0; qi < 4; qi++) {
        int row = m0 + ty * 4 + qi;
        if (row >= M) continue;
        #pragma unroll
        for (int ni = 0; ni < 4; ni++) {
            int col = n0 + tx * 4 + ni;
            if (col >= N) continue;
            float v = acc[qi][ni] + bias[col];
            if (mode == 0) {
                int which = col / DIM_;
                int rem   = col - which * DIM_;
                int head  = rem / HD_;
                int c     = rem - head * HD_;
                g_raw[((which * 2 + head) * NTOK + row) * HD_ + c] = v;
            } else {
                out[row * N + col] = v;
            }
        }
    }
}

// ---------------------------------------------------------------------------
// Attention pool: 3x3x3 depthwise conv on spatial tokens + LayerNorm(96)
// grid: (NTOK, 6)  block: 96  — blockIdx.y = tensor*2 + head
// ---------------------------------------------------------------------------
__global__ __launch_bounds__(96) void pool_kernel(
    const float* __restrict__ wq, const float* __restrict__ wk, const float* __restrict__ wv,
    const float* __restrict__ gq, const float* __restrict__ bq,
    const float* __restrict__ gk, const float* __restrict__ bk,
    const float* __restrict__ gv, const float* __restrict__ bv)
{
    int tok = blockIdx.x;
    int yy  = blockIdx.y;
    int tensor = yy >> 1, head = yy & 1;
    int c = threadIdx.x;

    const float* in = g_raw + (tensor * 2 + head) * NTOK * HD_;
    const float* wc = (tensor == 0) ? wq : (tensor == 1) ? wk : wv;
    const float* g  = (tensor == 0) ? gq : (tensor == 1) ? gk : gv;
    const float* b  = (tensor == 0) ? bq : (tensor == 1) ? bk : bv;

    float val;
    if (tok == 0) {
        val = in[c];
    } else {
        int s = tok - 1;
        int t = s / 784; int r = s - t * 784;
        int h = r / 28;  int w = r - h * 28;
        val = 0.f;
        #pragma unroll
        for (int dt = -1; dt <= 1; dt++) {
            int tt = t + dt; if ((unsigned)tt >= (unsigned)T_) continue;
            #pragma unroll
            for (int dh = -1; dh <= 1; dh++) {
                int hh = h + dh; if ((unsigned)hh >= (unsigned)H_) continue;
                #pragma unroll
                for (int dw = -1; dw <= 1; dw++) {
                    int ww = w + dw; if ((unsigned)ww >= (unsigned)W_) continue;
                    int nb = 1 + (tt * 28 + hh) * 28 + ww;
                    val += in[nb * HD_ + c] * wc[c * 27 + (dt+1)*9 + (dh+1)*3 + (dw+1)];
                }
            }
        }
    }

    __shared__ float red[96], red2[96];
    red[c] = val; red2[c] = val * val;
    __syncthreads();
    if (c < 48) { red[c] += red[c+48]; red2[c] += red2[c+48]; } __syncthreads();
    if (c < 24) { red[c] += red[c+24]; red2[c] += red2[c+24]; } __syncthreads();
    if (c < 12) { red[c] += red[c+12]; red2[c] += red2[c+12]; } __syncthreads();
    if (c <  6) { red[c] += red[c+ 6]; red2[c] += red2[c+ 6]; } __syncthreads();
    if (c <  3) { red[c] += red[c+ 3]; red2[c] += red2[c+ 3]; } __syncthreads();

    float mean = (red[0]  + red[1]  + red[2])  * (1.f / 96.f);
    float ms   = (red2[0] + red2[1] + red2[2]) * (1.f / 96.f);
    float var  = ms - mean * mean;
    float o = (val - mean) * rsqrtf(var + 1e-5f) * g[c] + b[c];
    g_pool[(tensor * 2 + head) * NTOK * HD_ + tok * HD_ + c] = o;
}

// ---------------------------------------------------------------------------
__global__ void zero_bias_kernel() {
    int i = blockIdx.x * 256 + threadIdx.x;
    if (i < 2 * NTOK * BROW) g_bias[i] = 0.f;
}

// Decomposed rel-bias precompute: per (head, spatial query): 64 dot products.
// grid: (SP_, 2)  block: 64
__global__ __launch_bounds__(64) void bias_kernel(
    const float* __restrict__ rel_h, const float* __restrict__ rel_w,
    const float* __restrict__ rel_t)
{
    int s = blockIdx.x; int head = blockIdx.y;
    int t = s / 784; int r = s - t * 784;
    int h = r / 28;  int w = r - h * 28;

    __shared__ float qs[96];
    const float* qp = g_pool + head * NTOK * HD_ + (s + 1) * HD_;
    for (int i = threadIdx.x; i < 96; i += 64) qs[i] = qp[i];
    __syncthreads();

    int i = threadIdx.x;
    const float* rel; int ridx;
    if (i < 8)       { rel = rel_t; ridx = t - i + 7; }
    else if (i < 36) { rel = rel_h; ridx = h - (i - 8) + 27; }
    else             { rel = rel_w; ridx = w - (i - 36) + 27; }
    const float* rr = rel + ridx * 96;

    float sum = 0.f;
    #pragma unroll
    for (int c = 0; c < 96; c += 4)
        sum += qs[c]*rr[c] + qs[c+1]*rr[c+1] + qs[c+2]*rr[c+2] + qs[c+3]*rr[c+3];

    g_bias[(head * NTOK + s + 1) * BROW + i] = sum;
}

// ---------------------------------------------------------------------------
// Flash attention: Mq=64 x Nk=64 tiles, online softmax, bias via table lookup.
// grid: (ceil(NTOK/64), 2)  block: 256  dyn smem 91136 B
// ---------------------------------------------------------------------------
__global__ __launch_bounds__(256, 2) void flash_kernel()
{
    extern __shared__ float sm[];
    float* sQ = sm;            // [96][64] transposed
    float* sK = sm + 6144;     // [96][64] transposed
    float* sV = sm + 12288;    // [64][SV_STRIDE]
    float* sP = sm + 12288 + 64 * SV_STRIDE;  // [64][64]

    int head = blockIdx.y;
    int q0   = blockIdx.x * 64;
    int tid  = threadIdx.x;
    int tx = tid & 15, ty = tid >> 4;

    const float* qp = g_pool + (0 + head) * NTOK * HD_;
    const float* kp = g_pool + (2 + head) * NTOK * HD_;
    const float* vp = g_pool + (4 + head) * NTOK * HD_;

    // Load Q tile transposed
    {
        int n = tid & 63, c4b = tid >> 6;
        int row = q0 + n;
        bool ok = row < NTOK;
        for (int c4 = c4b; c4 < 24; c4 += 4) {
            float4 v = ok ? *(const float4*)&qp[row * HD_ + c4 * 4]
                          : make_float4(0.f, 0.f, 0.f, 0.f);
            sQ[(c4*4+0)*64+n] = v.x; sQ[(c4*4+1)*64+n] = v.y;
            sQ[(c4*4+2)*64+n] = v.z; sQ[(c4*4+3)*64+n] = v.w;
        }
    }

    float m_r[4], l_r[4], oacc[4][6];
    #pragma unroll
    for (int qi = 0; qi < 4; qi++) {
        m_r[qi] = -1e30f; l_r[qi] = 0.f;
        #pragma unroll
        for (int cj = 0; cj < 6; cj++) oacc[qi][cj] = 0.f;
    }

    const float* __restrict__ Brow[4];
    #pragma unroll
    for (int qi = 0; qi < 4; qi++) {
        int q = q0 + ty * 4 + qi; if (q >= NTOK) q = NTOK - 1;
        Brow[qi] = g_bias + (head * NTOK + q) * BROW;
    }

    for (int k0 = 0; k0 < NTOK; k0 += 64) {
        __syncthreads();
        // Load K (transposed) and V (row-major, padded stride)
        {
            int n = tid & 63, c4b = tid >> 6;
            int row = k0 + n;
            bool ok = row < NTOK;
            for (int c4 = c4b; c4 < 24; c4 += 4) {
                float4 v = ok ? *(const float4*)&kp[row * HD_ + c4 * 4]
                              : make_float4(0.f, 0.f, 0.f, 0.f);
                sK[(c4*4+0)*64+n] = v.x; sK[(c4*4+1)*64+n] = v.y;
                sK[(c4*4+2)*64+n] = v.z; sK[(c4*4+3)*64+n] = v.w;
                float4 u = ok ? *(const float4*)&vp[row * HD_ + c4 * 4]
                              : make_float4(0.f, 0.f, 0.f, 0.f);
                *(float4*)&sV[n * SV_STRIDE + c4 * 4] = u;
            }
        }
        __syncthreads();

        // S = Q K^T
        float acc[4][4] = {};
        #pragma unroll 4
        for (int c = 0; c < 96; c++) {
            float4 a = *(float4*)&sQ[c * 64 + ty * 4];
            float4 b = *(float4*)&sK[c * 64 + tx * 4];
            acc[0][0] += a.x*b.x; acc[0][1] += a.x*b.y; acc[0][2] += a.x*b.z; acc[0][3] += a.x*b.w;
            acc[1][0] += a.y*b.x; acc[1][1] += a.y*b.y; acc[1][2] += a.y*b.z; acc[1][3] += a.y*b.w;
            acc[2][0] += a.z*b.x; acc[2][1] += a.z*b.y; acc[2][2] += a.z*b.z; acc[2][3] += a.z*b.w;
            acc[3][0] += a.w*b.x; acc[3][1] += a.w*b.y; acc[3][2] += a.w*b.z; acc[3][3] += a.w*b.w;
        }

        // scale + rel bias + key mask
        #pragma unroll
        for (int j = 0; j < 4; j++) {
            int kg = k0 + tx * 4 + j;
            bool valid = kg < NTOK;
            int i0, i1, i2;
            if (kg == 0) { i0 = 64; i1 = 65; i2 = 66; }
            else {
                int ss = kg - 1;
                i0 = ss / 784; int rr = ss - i0 * 784;
                int hh = rr / 28;
                i1 = 8 + hh;
                i2 = 36 + rr - hh * 28;
            }
            #pragma unroll
            for (int qi = 0; qi < 4; qi++) {
                float bi = Brow[qi][i0] + Brow[qi][i1] + Brow[qi][i2];
                acc[qi][j] = valid ? acc[qi][j] * SCALE_ + bi : -1e30f;
            }
        }

        // row max across the 16 tx lanes owning this row (within half-warp)
        float rmax[4];
        #pragma unroll
        for (int qi = 0; qi < 4; qi++)
            rmax[qi] = fmaxf(fmaxf(acc[qi][0], acc[qi][1]), fmaxf(acc[qi][2], acc[qi][3]));
        #pragma unroll
        for (int o = 1; o < 16; o <<= 1) {
            #pragma unroll
            for (int qi = 0; qi < 4; qi++)
                rmax[qi] = fmaxf(rmax[qi], __shfl_xor_sync(0xffffffffu, rmax[qi], o));
        }

        float nm[4], corr[4], psum[4];
        #pragma unroll
        for (int qi = 0; qi < 4; qi++) {
            nm[qi]   = fmaxf(m_r[qi], rmax[qi]);
            corr[qi] = __expf(m_r[qi] - nm[qi]);
            m_r[qi]  = nm[qi];
        }

        #pragma unroll
        for (int qi = 0; qi < 4; qi++) {
            float4 p;
            p.x = __expf(acc[qi][0] - nm[qi]);
            p.y = __expf(acc[qi][1] - nm[qi]);
            p.z = __expf(acc[qi][2] - nm[qi]);
            p.w = __expf(acc[qi][3] - nm[qi]);
            psum[qi] = (p.x + p.y) + (p.z + p.w);
            *(float4*)&sP[(ty * 4 + qi) * 64 + tx * 4] = p;
        }
        #pragma unroll
        for (int o = 1; o < 16; o <<= 1) {
            #pragma unroll
            for (int qi = 0; qi < 4; qi++)
                psum[qi] += __shfl_xor_sync(0xffffffffu, psum[qi], o);
        }
        #pragma unroll
        for (int qi = 0; qi < 4; qi++) {
            l_r[qi] = l_r[qi] * corr[qi] + psum[qi];
            #pragma unroll
            for (int cj = 0; cj < 6; cj++) oacc[qi][cj] *= corr[qi];
        }
        __syncwarp();

        // O += P @ V
        #pragma unroll 4
        for (int j = 0; j < 64; j++) {
            float p0 = sP[(ty*4+0)*64 + j];
            float p1 = sP[(ty*4+1)*64 + j];
            float p2 = sP[(ty*4+2)*64 + j];
            float p3 = sP[(ty*4+3)*64 + j];
            const float* vr = &sV[j * SV_STRIDE + tx * 6];
            float v0 = vr[0], v1 = vr[1], v2 = vr[2], v3 = vr[3], v4 = vr[4], v5 = vr[5];
            oacc[0][0]+=p0*v0; oacc[0][1]+=p0*v1; oacc[0][2]+=p0*v2; oacc[0][3]+=p0*v3; oacc[0][4]+=p0*v4; oacc[0][5]+=p0*v5;
            oacc[1][0]+=p1*v0; oacc[1][1]+=p1*v1; oacc[1][2]+=p1*v2; oacc[1][3]+=p1*v3; oacc[1][4]+=p1*v4; oacc[1][5]+=p1*v5;
            oacc[2][0]+=p2*v0; oacc[2][1]+=p2*v1; oacc[2][2]+=p2*v2; oacc[2][3]+=p2*v3; oacc[2][4]+=p2*v4; oacc[2][5]+=p2*v5;
            oacc[3][0]+=p3*v0; oacc[3][1]+=p3*v1; oacc[3][2]+=p3*v2; oacc[3][3]+=p3*v3; oacc[3][4]+=p3*v4; oacc[3][5]+=p3*v5;
        }
    }

    // epilogue: normalize, residual (pooled q, spatial rows only), store
    #pragma unroll
    for (int qi = 0; qi < 4; qi++) {
        int q = q0 + ty * 4 + qi;
        if (q >= NTOK) continue;
        float invl = 1.0f / l_r[qi];
        const float* res = qp + q * HD_;
        #pragma unroll
        for (int cj = 0; cj < 6; cj++) {
            int c = tx * 6 + cj;
            float v = oacc[qi][cj] * invl;
            if (q >= 1) v += res[c];
            g_att[q * DIM_ + head * HD_ + c] = v;
        }
    }
}

// ---------------------------------------------------------------------------
extern "C" void kernel_launch(void* const* d_in, const int* in_sizes, int n_in,
                              void* d_out, int out_size)
{
    const float* x      = (const float*)d_in[0];
    const float* qkv_w  = (const float*)d_in[1];
    const float* qkv_b  = (const float*)d_in[2];
    const float* proj_w = (const float*)d_in[3];
    const float* proj_b = (const float*)d_in[4];
    const float* pqw    = (const float*)d_in[5];
    const float* pkw    = (const float*)d_in[6];
    const float* pvw    = (const float*)d_in[7];
    const float* nqg    = (const float*)d_in[8];
    const float* nqb    = (const float*)d_in[9];
    const float* nkg    = (const float*)d_in[10];
    const float* nkb    = (const float*)d_in[11];
    const float* nvg    = (const float*)d_in[12];
    const float* nvb    = (const float*)d_in[13];
    const float* rel_h  = (const float*)d_in[14];
    const float* rel_w  = (const float*)d_in[15];
    const float* rel_t  = (const float*)d_in[16];
    float* out = (float*)d_out;

    const int smem_flash = (12288 + 64 * SV_STRIDE + 64 * 64) * 4;
    cudaFuncSetAttribute(flash_kernel, cudaFuncAttributeMaxDynamicSharedMemorySize, smem_flash);

    dim3 g1(99, 9);
    gemm_kernel<<<g1, 256>>>(x, qkv_w, qkv_b, nullptr, NTOK, 576, 0);

    dim3 g2(NTOK, 6);
    pool_kernel<<<g2, 96>>>(pqw, pkw, pvw, nqg, nqb, nkg, nkb, nvg, nvb);

    zero_bias_kernel<<<(2 * NTOK * BROW + 255) / 256, 256>>>();

    dim3 g3(SP_, 2);
    bias_kernel<<<g3, 64>>>(rel_h, rel_w, rel_t);

    dim3 g4(99, 2);
    flash_kernel<<<g4, 256, smem_flash>>>();

    dim3 g5(99, 3);
    gemm_kernel<<<g5, 256>>>(nullptr, proj_w, proj_b, out, NTOK, 192, 1);
}

// round 2
// speedup vs baseline: 2.4334x; 2.4334x over previous
#include <cuda_runtime.h>
#include <math.h>

#define T_    8
#define H_    28
#define W_    28
#define SP_   6272
#define NTOK  6273
#define DIM_  192
#define HD_   96
#define BROW  68
#define SCALE_ 0.1020620726159658f   // 96^-0.5
#define LOG2E  1.4426950408889634f
#define SCL2   (SCALE_ * LOG2E)

// Scratch (static device memory — no allocations)
__device__ float g_raw [6 * NTOK * HD_];   // [which*2+head][tok][c]  pre-pool q,k,v
__device__ float g_pool[6 * NTOK * HD_];   // pooled+LN q,k,v
__device__ float g_bias[2 * NTOK * BROW];  // per (head,q): [0..7]=Bt [8..35]=Bh [36..63]=Bw [64..67]=0  (×LOG2E)
__device__ float g_att [NTOK * DIM_];      // attention output + residual

// ---------------------------------------------------------------------------
__device__ __forceinline__ float cvt_tf32(float x) {
    unsigned u; asm("cvt.rna.tf32.f32 %0, %1;" : "=r"(u) : "f"(x));
    return __uint_as_float(u);
}
__device__ __forceinline__ float fexp2(float x) {
    float y; asm("ex2.approx.ftz.f32 %0, %1;" : "=f"(y) : "f"(x)); return y;
}
__device__ __forceinline__ void mma8(float* d, const float4& a, const float2& b) {
    asm volatile("mma.sync.aligned.m16n8k8.row.col.f32.tf32.tf32.f32 "
        "{%0,%1,%2,%3}, {%4,%5,%6,%7}, {%8,%9}, {%0,%1,%2,%3};"
        : "+f"(d[0]), "+f"(d[1]), "+f"(d[2]), "+f"(d[3])
        : "r"(__float_as_uint(a.x)), "r"(__float_as_uint(a.y)),
          "r"(__float_as_uint(a.z)), "r"(__float_as_uint(a.w)),
          "r"(__float_as_uint(b.x)), "r"(__float_as_uint(b.y)));
}

// ---------------------------------------------------------------------------
// Tiled SGEMM: C[M x N] = A[M x 192] @ Bm[N x 192]^T + bias
// ---------------------------------------------------------------------------
__global__ __launch_bounds__(256) void gemm_kernel(
    const float* __restrict__ A, const float* __restrict__ Bm,
    const float* __restrict__ bias, float* __restrict__ out,
    int M, int N, int mode)
{
    __shared__ float sA[16][64];
    __shared__ float sB[16][64];
    const int K = 192;
    const float* Ap = (mode == 1) ? g_att : A;

    int tid = threadIdx.x;
    int tx = tid & 15, ty = tid >> 4;
    int m0 = blockIdx.x * 64, n0 = blockIdx.y * 64;
    int lr = tid >> 2;
    int lc = tid & 3;

    float acc[4][4] = {};

    for (int k0 = 0; k0 < K; k0 += 16) {
        {
            int row = m0 + lr;
            float4 v = make_float4(0.f, 0.f, 0.f, 0.f);
            if (row < M) v = *(const float4*)&Ap[row * K + k0 + lc * 4];
            sA[lc*4+0][lr] = v.x; sA[lc*4+1][lr] = v.y;
            sA[lc*4+2][lr] = v.z; sA[lc*4+3][lr] = v.w;
        }
        {
            int row = n0 + lr;
            float4 v = make_float4(0.f, 0.f, 0.f, 0.f);
            if (row < N) v = *(const float4*)&Bm[row * K + k0 + lc * 4];
            sB[lc*4+0][lr] = v.x; sB[lc*4+1][lr] = v.y;
            sB[lc*4+2][lr] = v.z; sB[lc*4+3][lr] = v.w;
        }
        __syncthreads();
        #pragma unroll
        for (int kk = 0; kk < 16; kk++) {
            float4 a = *(float4*)&sA[kk][ty * 4];
            float4 b = *(float4*)&sB[kk][tx * 4];
            acc[0][0] += a.x*b.x; acc[0][1] += a.x*b.y; acc[0][2] += a.x*b.z; acc[0][3] += a.x*b.w;
            acc[1][0] += a.y*b.x; acc[1][1] += a.y*b.y; acc[1][2] += a.y*b.z; acc[1][3] += a.y*b.w;
            acc[2][0] += a.z*b.x; acc[2][1] += a.z*b.y; acc[2][2] += a.z*b.z; acc[2][3] += a.z*b.w;
            acc[3][0] += a.w*b.x; acc[3][1] += a.w*b.y; acc[3][2] += a.w*b.z; acc[3][3] += a.w*b.w;
        }
        __syncthreads();
    }

    #pragma unroll
    for (int qi = 0; qi < 4; qi++) {
        int row = m0 + ty * 4 + qi;
        if (row >= M) continue;
        #pragma unroll
        for (int ni = 0; ni < 4; ni++) {
            int col = n0 + tx * 4 + ni;
            if (col >= N) continue;
            float v = acc[qi][ni] + bias[col];
            if (mode == 0) {
                int which = col / DIM_;
                int rem   = col - which * DIM_;
                int head  = rem / HD_;
                int c     = rem - head * HD_;
                g_raw[((which * 2 + head) * NTOK + row) * HD_ + c] = v;
            } else {
                out[row * N + col] = v;
            }
        }
    }
}

// ---------------------------------------------------------------------------
// Attention pool: 3x3x3 depthwise conv + LayerNorm(96)
// ---------------------------------------------------------------------------
__global__ __launch_bounds__(96) void pool_kernel(
    const float* __restrict__ wq, const float* __restrict__ wk, const float* __restrict__ wv,
    const float* __restrict__ gq, const float* __restrict__ bq,
    const float* __restrict__ gk, const float* __restrict__ bk,
    const float* __restrict__ gv, const float* __restrict__ bv)
{
    int tok = blockIdx.x;
    int yy  = blockIdx.y;
    int tensor = yy >> 1, head = yy & 1;
    int c = threadIdx.x;

    const float* in = g_raw + (tensor * 2 + head) * NTOK * HD_;
    const float* wc = (tensor == 0) ? wq : (tensor == 1) ? wk : wv;
    const float* g  = (tensor == 0) ? gq : (tensor == 1) ? gk : gv;
    const float* b  = (tensor == 0) ? bq : (tensor == 1) ? bk : bv;

    float val;
    if (tok == 0) {
        val = in[c];
    } else {
        int s = tok - 1;
        int t = s / 784; int r = s - t * 784;
        int h = r / 28;  int w = r - h * 28;
        val = 0.f;
        #pragma unroll
        for (int dt = -1; dt <= 1; dt++) {
            int tt = t + dt; if ((unsigned)tt >= (unsigned)T_) continue;
            #pragma unroll
            for (int dh = -1; dh <= 1; dh++) {
                int hh = h + dh; if ((unsigned)hh >= (unsigned)H_) continue;
                #pragma unroll
                for (int dw = -1; dw <= 1; dw++) {
                    int ww = w + dw; if ((unsigned)ww >= (unsigned)W_) continue;
                    int nb = 1 + (tt * 28 + hh) * 28 + ww;
                    val += in[nb * HD_ + c] * wc[c * 27 + (dt+1)*9 + (dh+1)*3 + (dw+1)];
                }
            }
        }
    }

    __shared__ float red[96], red2[96];
    red[c] = val; red2[c] = val * val;
    __syncthreads();
    if (c < 48) { red[c] += red[c+48]; red2[c] += red2[c+48]; } __syncthreads();
    if (c < 24) { red[c] += red[c+24]; red2[c] += red2[c+24]; } __syncthreads();
    if (c < 12) { red[c] += red[c+12]; red2[c] += red2[c+12]; } __syncthreads();
    if (c <  6) { red[c] += red[c+ 6]; red2[c] += red2[c+ 6]; } __syncthreads();
    if (c <  3) { red[c] += red[c+ 3]; red2[c] += red2[c+ 3]; } __syncthreads();

    float mean = (red[0]  + red[1]  + red[2])  * (1.f / 96.f);
    float ms   = (red2[0] + red2[1] + red2[2]) * (1.f / 96.f);
    float var  = ms - mean * mean;
    float o = (val - mean) * rsqrtf(var + 1e-5f) * g[c] + b[c];
    g_pool[(tensor * 2 + head) * NTOK * HD_ + tok * HD_ + c] = o;
}

// ---------------------------------------------------------------------------
__global__ void zero_bias_kernel() {
    int i = blockIdx.x * 256 + threadIdx.x;
    if (i < 2 * NTOK * BROW) g_bias[i] = 0.f;
}

// Rel-bias precompute, smem-staged. grid (49, 2), block 256, dyn smem ~99KB.
// Output pre-multiplied by LOG2E.
#define RSTRIDE 100
__global__ __launch_bounds__(256) void bias_kernel(
    const float* __restrict__ rel_h, const float* __restrict__ rel_w,
    const float* __restrict__ rel_t)
{
    extern __shared__ float bsm[];
    float* sRel = bsm;               // 125 * 100
    float* sQ   = bsm + 125 * RSTRIDE;  // 128 * 96
    int head = blockIdx.y;
    int qb = blockIdx.x * 128;       // spatial s base
    int tid = threadIdx.x;
    const float* qp = g_pool + head * NTOK * HD_;

    for (int idx = tid; idx < 125 * 24; idx += 256) {
        int row = idx / 24, c4 = idx - row * 24;
        const float* src = row < 15 ? rel_t + row * 96
                         : row < 70 ? rel_h + (row - 15) * 96
                                    : rel_w + (row - 70) * 96;
        float4 v = *(const float4*)(src + c4 * 4);
        float* dst = sRel + row * RSTRIDE + c4 * 4;
        dst[0] = v.x * LOG2E; dst[1] = v.y * LOG2E;
        dst[2] = v.z * LOG2E; dst[3] = v.w * LOG2E;
    }
    for (int idx = tid; idx < 128 * 24; idx += 256) {
        int r = idx / 24, c4 = idx - r * 24;
        *(float4*)(sQ + r * 96 + c4 * 4) =
            *(const float4*)(qp + (qb + 1 + r) * 96 + c4 * 4);
    }
    __syncthreads();

    for (int it = tid; it < 128 * 64; it += 256) {
        int ql = it >> 6, i = it & 63;
        int s = qb + ql;
        int t = s / 784; int rr = s - t * 784;
        int h = rr / 28; int w = rr - h * 28;
        int row = (i < 8)  ? (t - i + 7)
                : (i < 36) ? 15 + (h - (i - 8) + 27)
                           : 70 + (w - (i - 36) + 27);
        const float* q4 = sQ + ql * 96;
        const float* r4 = sRel + row * RSTRIDE;
        float sum = 0.f;
        #pragma unroll
        for (int c = 0; c < 96; c += 4) {
            float4 a = *(const float4*)(q4 + c);
            float4 b = *(const float4*)(r4 + c);
            sum += a.x*b.x + a.y*b.y + a.z*b.z + a.w*b.w;
        }
        g_bias[(head * NTOK + s + 1) * BROW + i] = sum;
    }
}

// ---------------------------------------------------------------------------
// Flash attention with tf32 mma.sync: Mq=96 x Nk=64, 12 warps.
// grid (66, 2), block 384, dyn smem 138496 B.
// ---------------------------------------------------------------------------
__global__ __launch_bounds__(384, 1) void flash_mma_kernel()
{
    extern __shared__ float sm[];
    float* sQp = sm;              // 6 mtiles * 12 ks * 32 * 4 = 9216
    float* sKp = sm + 9216;       // 8 ntiles * 12 ks * 32 * 2 = 6144
    float* sVp = sm + 15360;      // 12 ntiles * 8 ks * 32 * 2 = 6144
    float* sPp = sm + 21504;      // 6 mtiles * 8 ks * 32 * 4 = 6144
    float* sB  = sm + 27648;      // 96 * 68 = 6528
    float* sRM = sm + 34176;      // 2 * 96
    float* sRS = sm + 34368;      // 2 * 96
    int*   sKI = (int*)(sm + 34560); // 64

    const int head = blockIdx.y;
    const int q0 = blockIdx.x * 96;
    const int tid = threadIdx.x;
    const int lane = tid & 31, warp = tid >> 5;
    const int mw = warp >> 1, nw = warp & 1;

    const float* qp = g_pool + head * NTOK * HD_;
    const float* kp = g_pool + (2 + head) * NTOK * HD_;
    const float* vp = g_pool + (4 + head) * NTOK * HD_;

    // Load Q into A-fragment-permuted layout (tf32)
    {
        int r = tid >> 2;     // 0..95
        int row = q0 + r;
        bool ok = row < NTOK;
        #pragma unroll
        for (int c4 = tid & 3; c4 < 24; c4 += 4) {
            float4 v = ok ? *(const float4*)(qp + row * 96 + c4 * 4)
                          : make_float4(0.f, 0.f, 0.f, 0.f);
            int qbase = ((r >> 4) * 12 + (c4 >> 1)) * 128 + (r & 7) * 16
                        + ((r >> 3) & 1) + 2 * (c4 & 1);
            sQp[qbase + 0]  = cvt_tf32(v.x);
            sQp[qbase + 4]  = cvt_tf32(v.y);
            sQp[qbase + 8]  = cvt_tf32(v.z);
            sQp[qbase + 12] = cvt_tf32(v.w);
        }
    }
    // Stage bias rows for this block's 96 queries
    for (int idx = tid; idx < 96 * 17; idx += 384) {
        int r = idx / 17, c4 = idx - r * 17;
        int row = q0 + r; if (row >= NTOK) row = NTOK - 1;
        *(float4*)(sB + r * 68 + c4 * 4) =
            *(const float4*)(g_bias + (head * NTOK + row) * BROW + c4 * 4);
    }

    float mA = -1e30f, mB = -1e30f, lA = 0.f, lB = 0.f;
    float oacc[6][4] = {};
    const int rloc = mw * 16 + (lane >> 2);
    const float* Br0 = sB + rloc * 68;
    const float* Br1 = Br0 + 8 * 68;

    for (int k0 = 0; k0 < NTOK; k0 += 64) {
        __syncthreads();
        // Load K, V permuted (tf32)
        {
            int r = tid & 63;
            int rowg = k0 + r;
            bool ok = rowg < NTOK;
            #pragma unroll
            for (int c4 = tid >> 6; c4 < 24; c4 += 6) {
                float4 kv = ok ? *(const float4*)(kp + rowg * 96 + c4 * 4)
                               : make_float4(0.f, 0.f, 0.f, 0.f);
                int kbase = ((r >> 3) * 12 + (c4 >> 1)) * 64 + (r & 7) * 8 + (c4 & 1);
                sKp[kbase + 0] = cvt_tf32(kv.x);
                sKp[kbase + 2] = cvt_tf32(kv.y);
                sKp[kbase + 4] = cvt_tf32(kv.z);
                sKp[kbase + 6] = cvt_tf32(kv.w);
                float4 vv = ok ? *(const float4*)(vp + rowg * 96 + c4 * 4)
                               : make_float4(0.f, 0.f, 0.f, 0.f);
                int vbase = ((c4 >> 1) * 8 + (r >> 3)) * 64 + (r & 3) * 2
                            + ((r >> 2) & 1) + (c4 & 1) * 32;
                sVp[vbase + 0]  = cvt_tf32(vv.x);
                sVp[vbase + 8]  = cvt_tf32(vv.y);
                sVp[vbase + 16] = cvt_tf32(vv.z);
                sVp[vbase + 24] = cvt_tf32(vv.w);
            }
        }
        if (tid < 64) {
            int kg = k0 + tid;
            int packed;
            if (kg >= NTOK) packed = -1;
            else if (kg == 0) packed = 64 | (65 << 8) | (66 << 16);
            else {
                int ss = kg - 1;
                int t = ss / 784; int rr2 = ss - t * 784;
                int hh = rr2 / 28; int ww = rr2 - hh * 28;
                packed = t | ((8 + hh) << 8) | ((36 + ww) << 16);
            }
            sKI[tid] = packed;
        }
        __syncthreads();

        // S = Q K^T  (tf32 mma)
        float d[4][4] = {};
        #pragma unroll
        for (int ks = 0; ks < 12; ks++) {
            float4 a = *(const float4*)(sQp + ((mw * 12 + ks) * 32 + lane) * 4);
            #pragma unroll
            for (int nt = 0; nt < 4; nt++) {
                float2 b = *(const float2*)(sKp + (((nw * 4 + nt) * 12 + ks) * 32 + lane) * 2);
                mma8(d[nt], a, b);
            }
        }

        // scale + bias + mask, track row max
        float rm0 = -1e30f, rm1 = -1e30f;
        #pragma unroll
        for (int nt = 0; nt < 4; nt++) {
            int c0 = nw * 32 + nt * 8 + (lane & 3) * 2;
            int p0 = sKI[c0], p1 = sKI[c0 + 1];
            if (p0 >= 0) {
                int i0 = p0 & 255, i1 = (p0 >> 8) & 255, i2 = p0 >> 16;
                d[nt][0] = d[nt][0] * SCL2 + (Br0[i0] + Br0[i1] + Br0[i2]);
                d[nt][2] = d[nt][2] * SCL2 + (Br1[i0] + Br1[i1] + Br1[i2]);
            } else { d[nt][0] = -1e30f; d[nt][2] = -1e30f; }
            if (p1 >= 0) {
                int i0 = p1 & 255, i1 = (p1 >> 8) & 255, i2 = p1 >> 16;
                d[nt][1] = d[nt][1] * SCL2 + (Br0[i0] + Br0[i1] + Br0[i2]);
                d[nt][3] = d[nt][3] * SCL2 + (Br1[i0] + Br1[i1] + Br1[i2]);
            } else { d[nt][1] = -1e30f; d[nt][3] = -1e30f; }
            rm0 = fmaxf(rm0, fmaxf(d[nt][0], d[nt][1]));
            rm1 = fmaxf(rm1, fmaxf(d[nt][2], d[nt][3]));
        }
        rm0 = fmaxf(rm0, __shfl_xor_sync(0xffffffffu, rm0, 1));
        rm0 = fmaxf(rm0, __shfl_xor_sync(0xffffffffu, rm0, 2));
        rm1 = fmaxf(rm1, __shfl_xor_sync(0xffffffffu, rm1, 1));
        rm1 = fmaxf(rm1, __shfl_xor_sync(0xffffffffu, rm1, 2));
        if ((lane & 3) == 0) {
            sRM[nw * 96 + rloc]     = rm0;
            sRM[nw * 96 + rloc + 8] = rm1;
        }
        __syncthreads();
        rm0 = fmaxf(rm0, sRM[(1 - nw) * 96 + rloc]);
        rm1 = fmaxf(rm1, sRM[(1 - nw) * 96 + rloc + 8]);
        float nm0 = fmaxf(mA, rm0), nm1 = fmaxf(mB, rm1);
        float cf0 = fexp2(mA - nm0), cf1 = fexp2(mB - nm1);
        mA = nm0; mB = nm1;

        float s0 = 0.f, s1 = 0.f;
        #pragma unroll
        for (int nt = 0; nt < 4; nt++) {
            float p00 = fexp2(d[nt][0] - nm0), p01 = fexp2(d[nt][1] - nm0);
            float p10 = fexp2(d[nt][2] - nm1), p11 = fexp2(d[nt][3] - nm1);
            s0 += p00 + p01; s1 += p10 + p11;
            int kk0 = (lane & 3) * 2;
            int base = ((mw * 8 + nw * 4 + nt) * 32 + (lane >> 2) * 4 + (kk0 & 3)) * 4
                       + 2 * (kk0 >> 2);
            sPp[base]     = cvt_tf32(p00);
            sPp[base + 1] = cvt_tf32(p10);
            sPp[base + 4] = cvt_tf32(p01);
            sPp[base + 5] = cvt_tf32(p11);
        }
        s0 += __shfl_xor_sync(0xffffffffu, s0, 1);
        s0 += __shfl_xor_sync(0xffffffffu, s0, 2);
        s1 += __shfl_xor_sync(0xffffffffu, s1, 1);
        s1 += __shfl_xor_sync(0xffffffffu, s1, 2);
        if ((lane & 3) == 0) {
            sRS[nw * 96 + rloc]     = s0;
            sRS[nw * 96 + rloc + 8] = s1;
        }
        __syncthreads();
        lA = lA * cf0 + s0 + sRS[(1 - nw) * 96 + rloc];
        lB = lB * cf1 + s1 + sRS[(1 - nw) * 96 + rloc + 8];
        #pragma unroll
        for (int nt = 0; nt < 6; nt++) {
            oacc[nt][0] *= cf0; oacc[nt][1] *= cf0;
            oacc[nt][2] *= cf1; oacc[nt][3] *= cf1;
        }
        // O += P V (tf32 mma)
        #pragma unroll
        for (int ks = 0; ks < 8; ks++) {
            float4 a = *(const float4*)(sPp + ((mw * 8 + ks) * 32 + lane) * 4);
            #pragma unroll
            for (int nt = 0; nt < 6; nt++) {
                float2 b = *(const float2*)(sVp + (((nw * 6 + nt) * 8 + ks) * 32 + lane) * 2);
                mma8(oacc[nt], a, b);
            }
        }
    }

    // epilogue: normalize, residual, store
    int r0 = q0 + mw * 16 + (lane >> 2);
    int r1 = r0 + 8;
    float il0 = 1.f / lA, il1 = 1.f / lB;
    #pragma unroll
    for (int nt = 0; nt < 6; nt++) {
        int c = nw * 48 + nt * 8 + (lane & 3) * 2;
        if (r0 < NTOK) {
            float e0 = (r0 >= 1) ? qp[r0 * 96 + c]     : 0.f;
            float e1 = (r0 >= 1) ? qp[r0 * 96 + c + 1] : 0.f;
            g_att[r0 * 192 + head * 96 + c]     = oacc[nt][0] * il0 + e0;
            g_att[r0 * 192 + head * 96 + c + 1] = oacc[nt][1] * il0 + e1;
        }
        if (r1 < NTOK) {
            g_att[r1 * 192 + head * 96 + c]     = oacc[nt][2] * il1 + qp[r1 * 96 + c];
            g_att[r1 * 192 + head * 96 + c + 1] = oacc[nt][3] * il1 + qp[r1 * 96 + c + 1];
        }
    }
}

// ---------------------------------------------------------------------------
extern "C" void kernel_launch(void* const* d_in, const int* in_sizes, int n_in,
                              void* d_out, int out_size)
{
    const float* x      = (const float*)d_in[0];
    const float* qkv_w  = (const float*)d_in[1];
    const float* qkv_b  = (const float*)d_in[2];
    const float* proj_w = (const float*)d_in[3];
    const float* proj_b = (const float*)d_in[4];
    const float* pqw    = (const float*)d_in[5];
    const float* pkw    = (const float*)d_in[6];
    const float* pvw    = (const float*)d_in[7];
    const float* nqg    = (const float*)d_in[8];
    const float* nqb    = (const float*)d_in[9];
    const float* nkg    = (const float*)d_in[10];
    const float* nkb    = (const float*)d_in[11];
    const float* nvg    = (const float*)d_in[12];
    const float* nvb    = (const float*)d_in[13];
    const float* rel_h  = (const float*)d_in[14];
    const float* rel_w  = (const float*)d_in[15];
    const float* rel_t  = (const float*)d_in[16];
    float* out = (float*)d_out;

    const int smem_flash = 34624 * 4;                       // 138496 B
    const int smem_bias  = (125 * RSTRIDE + 128 * 96) * 4;  // 99152 B
    cudaFuncSetAttribute(flash_mma_kernel, cudaFuncAttributeMaxDynamicSharedMemorySize, smem_flash);
    cudaFuncSetAttribute(bias_kernel, cudaFuncAttributeMaxDynamicSharedMemorySize, smem_bias);

    dim3 g1(99, 9);
    gemm_kernel<<<g1, 256>>>(x, qkv_w, qkv_b, nullptr, NTOK, 576, 0);

    dim3 g2(NTOK, 6);
    pool_kernel<<<g2, 96>>>(pqw, pkw, pvw, nqg, nqb, nkg, nkb, nvg, nvb);

    zero_bias_kernel<<<(2 * NTOK * BROW + 255) / 256, 256>>>();

    dim3 g3(49, 2);
    bias_kernel<<<g3, 256, smem_bias>>>(rel_h, rel_w, rel_t);

    dim3 g4(66, 2);
    flash_mma_kernel<<<g4, 384, smem_flash>>>();

    dim3 g5(99, 3);
    gemm_kernel<<<g5, 256>>>(nullptr, proj_w, proj_b, out, NTOK, 192, 1);
}

// round 4
// speedup vs baseline: 3.1679x; 1.3019x over previous
#include <cuda_runtime.h>
#include <cuda_bf16.h>
#include <math.h>

#define T_    8
#define H_    28
#define W_    28
#define SP_   6272
#define NTOK  6273
#define DIM_  192
#define HD_   96
#define BROW  68
#define SCALE_ 0.1020620726159658f   // 96^-0.5
#define LOG2E  1.4426950408889634f
#define SCL2   (SCALE_ * LOG2E)

// Scratch (static device memory — no allocations)
__device__ float g_raw [6 * NTOK * HD_];   // [which*2+head][tok][c]  pre-pool q,k,v
__device__ float g_pool[6 * NTOK * HD_];   // pooled+LN q,k,v
__device__ float g_bias[2 * NTOK * BROW];  // per (head,q): [0..7]=Bt [8..35]=Bh [36..63]=Bw [64..67]=0  (×LOG2E)
__device__ float g_att [NTOK * DIM_];      // attention output + residual

// ---------------------------------------------------------------------------
__device__ __forceinline__ float cvt_tf32(float x) {
    unsigned u; asm("cvt.rna.tf32.f32 %0, %1;" : "=r"(u) : "f"(x));
    return __uint_as_float(u);
}
__device__ __forceinline__ float fexp2(float x) {
    float y; asm("ex2.approx.ftz.f32 %0, %1;" : "=f"(y) : "f"(x)); return y;
}
__device__ __forceinline__ unsigned pack_bf16(float x, float y) {
    __nv_bfloat162 h = __float22bfloat162_rn(make_float2(x, y));
    return *(unsigned*)&h;
}
// tf32 m16n8k8
__device__ __forceinline__ void mma8(float* d, const float4& a, const float2& b) {
    asm volatile("mma.sync.aligned.m16n8k8.row.col.f32.tf32.tf32.f32 "
        "{%0,%1,%2,%3}, {%4,%5,%6,%7}, {%8,%9}, {%0,%1,%2,%3};"
        : "+f"(d[0]), "+f"(d[1]), "+f"(d[2]), "+f"(d[3])
        : "r"(__float_as_uint(a.x)), "r"(__float_as_uint(a.y)),
          "r"(__float_as_uint(a.z)), "r"(__float_as_uint(a.w)),
          "r"(__float_as_uint(b.x)), "r"(__float_as_uint(b.y)));
}
// bf16 m16n8k16
__device__ __forceinline__ void mma16(float* d, const float4& a, const float2& b) {
    asm volatile("mma.sync.aligned.m16n8k16.row.col.f32.bf16.bf16.f32 "
        "{%0,%1,%2,%3}, {%4,%5,%6,%7}, {%8,%9}, {%0,%1,%2,%3};"
        : "+f"(d[0]), "+f"(d[1]), "+f"(d[2]), "+f"(d[3])
        : "r"(__float_as_uint(a.x)), "r"(__float_as_uint(a.y)),
          "r"(__float_as_uint(a.z)), "r"(__float_as_uint(a.w)),
          "r"(__float_as_uint(b.x)), "r"(__float_as_uint(b.y)));
}

// ---------------------------------------------------------------------------
// tf32 mma GEMM: C[M x N] = A[M x 192] @ Bm[N x 192]^T + bias
// 64x64 tile, 256 threads (8 warps: 4 mtiles x 2 n-halves), K in 2 chunks of 96.
// mode 0: scatter into g_raw (qkv).  mode 1: A := g_att, write out row-major.
// ---------------------------------------------------------------------------
__global__ __launch_bounds__(256) void gemm_mma_kernel(
    const float* __restrict__ A, const float* __restrict__ Bm,
    const float* __restrict__ bias, float* __restrict__ out,
    int M, int N, int mode)
{
    __shared__ float sA[6144];   // 4 mtiles * 12 k8 * 128
    __shared__ float sB[6144];   // 8 ntiles * 12 k8 * 64
    const float* Ap = (mode == 1) ? g_att : A;

    int tid = threadIdx.x, lane = tid & 31, warp = tid >> 5;
    int mw = warp >> 1, nh = warp & 1;
    int m0 = blockIdx.x * 64, n0 = blockIdx.y * 64;

    float d[4][4] = {};

    for (int k0 = 0; k0 < 192; k0 += 96) {
        __syncthreads();
        {   // stage A chunk (tf32, A-fragment permuted)
            int r_g = tid >> 2, r = r_g & 15, mt = r_g >> 4;
            int row = m0 + r_g; if (row >= M) row = M - 1;
            #pragma unroll
            for (int c4 = tid & 3; c4 < 24; c4 += 4) {
                float4 v = *(const float4*)(Ap + row * 192 + k0 + c4 * 4);
                int base = (mt * 12 + (c4 >> 1)) * 128 + (r & 7) * 16
                           + ((r >> 3) & 1) + 2 * (c4 & 1);
                sA[base + 0]  = cvt_tf32(v.x); sA[base + 4]  = cvt_tf32(v.y);
                sA[base + 8]  = cvt_tf32(v.z); sA[base + 12] = cvt_tf32(v.w);
            }
        }
        {   // stage B chunk (tf32, B-fragment permuted)
            int r_g = tid >> 2;             // weight row 0..63
            int nt = r_g >> 3, gn = r_g & 7;
            #pragma unroll
            for (int c4 = tid & 3; c4 < 24; c4 += 4) {
                float4 v = *(const float4*)(Bm + (n0 + r_g) * 192 + k0 + c4 * 4);
                int base = (nt * 12 + (c4 >> 1)) * 64 + gn * 8 + (c4 & 1);
                sB[base + 0] = cvt_tf32(v.x); sB[base + 2] = cvt_tf32(v.y);
                sB[base + 4] = cvt_tf32(v.z); sB[base + 6] = cvt_tf32(v.w);
            }
        }
        __syncthreads();
        #pragma unroll
        for (int kt = 0; kt < 12; kt++) {
            float4 a = *(const float4*)(sA + ((mw * 12 + kt) * 32 + lane) * 4);
            #pragma unroll
            for (int nt = 0; nt < 4; nt++) {
                float2 b = *(const float2*)(sB + (((nh * 4 + nt) * 12 + kt) * 32 + lane) * 2);
                mma8(d[nt], a, b);
            }
        }
    }

    int g = lane >> 2, tq = lane & 3;
    int r0 = m0 + mw * 16 + g, r1 = r0 + 8;
    #pragma unroll
    for (int nt = 0; nt < 4; nt++) {
        int col = n0 + nh * 32 + nt * 8 + tq * 2;
        #pragma unroll
        for (int e = 0; e < 2; e++) {
            int c = col + e;
            float b = bias[c];
            float v0 = d[nt][e]     + b;
            float v1 = d[nt][e + 2] + b;
            if (mode == 0) {
                int which = c / DIM_;
                int rem   = c - which * DIM_;
                int head  = rem / HD_;
                int cc    = rem - head * HD_;
                int base  = (which * 2 + head) * NTOK * HD_ + cc;
                if (r0 < M) g_raw[base + r0 * HD_] = v0;
                if (r1 < M) g_raw[base + r1 * HD_] = v1;
            } else {
                if (r0 < M) out[r0 * N + c] = v0;
                if (r1 < M) out[r1 * N + c] = v1;
            }
        }
    }
}

// ---------------------------------------------------------------------------
// Attention pool: 3x3x3 depthwise conv + LayerNorm(96)
// ---------------------------------------------------------------------------
__global__ __launch_bounds__(96) void pool_kernel(
    const float* __restrict__ wq, const float* __restrict__ wk, const float* __restrict__ wv,
    const float* __restrict__ gq, const float* __restrict__ bq,
    const float* __restrict__ gk, const float* __restrict__ bk,
    const float* __restrict__ gv, const float* __restrict__ bv)
{
    int tok = blockIdx.x;
    int yy  = blockIdx.y;
    int tensor = yy >> 1, head = yy & 1;
    int c = threadIdx.x;

    const float* in = g_raw + (tensor * 2 + head) * NTOK * HD_;
    const float* wc = (tensor == 0) ? wq : (tensor == 1) ? wk : wv;
    const float* g  = (tensor == 0) ? gq : (tensor == 1) ? gk : gv;
    const float* b  = (tensor == 0) ? bq : (tensor == 1) ? bk : bv;

    float val;
    if (tok == 0) {
        val = in[c];
    } else {
        int s = tok - 1;
        int t = s / 784; int r = s - t * 784;
        int h = r / 28;  int w = r - h * 28;
        val = 0.f;
        #pragma unroll
        for (int dt = -1; dt <= 1; dt++) {
            int tt = t + dt; if ((unsigned)tt >= (unsigned)T_) continue;
            #pragma unroll
            for (int dh = -1; dh <= 1; dh++) {
                int hh = h + dh; if ((unsigned)hh >= (unsigned)H_) continue;
                #pragma unroll
                for (int dw = -1; dw <= 1; dw++) {
                    int ww = w + dw; if ((unsigned)ww >= (unsigned)W_) continue;
                    int nb = 1 + (tt * 28 + hh) * 28 + ww;
                    val += in[nb * HD_ + c] * wc[c * 27 + (dt+1)*9 + (dh+1)*3 + (dw+1)];
                }
            }
        }
    }

    __shared__ float red[96], red2[96];
    red[c] = val; red2[c] = val * val;
    __syncthreads();
    if (c < 48) { red[c] += red[c+48]; red2[c] += red2[c+48]; } __syncthreads();
    if (c < 24) { red[c] += red[c+24]; red2[c] += red2[c+24]; } __syncthreads();
    if (c < 12) { red[c] += red[c+12]; red2[c] += red2[c+12]; } __syncthreads();
    if (c <  6) { red[c] += red[c+ 6]; red2[c] += red2[c+ 6]; } __syncthreads();
    if (c <  3) { red[c] += red[c+ 3]; red2[c] += red2[c+ 3]; } __syncthreads();

    float mean = (red[0]  + red[1]  + red[2])  * (1.f / 96.f);
    float ms   = (red2[0] + red2[1] + red2[2]) * (1.f / 96.f);
    float var  = ms - mean * mean;
    float o = (val - mean) * rsqrtf(var + 1e-5f) * g[c] + b[c];
    g_pool[(tensor * 2 + head) * NTOK * HD_ + tok * HD_ + c] = o;
}

// ---------------------------------------------------------------------------
// Rel-bias precompute, smem-staged; also zeroes pad cols + cls row.
// grid (49, 2), block 256. Output pre-multiplied by LOG2E.
#define RSTRIDE 100
__global__ __launch_bounds__(256) void bias_kernel(
    const float* __restrict__ rel_h, const float* __restrict__ rel_w,
    const float* __restrict__ rel_t)
{
    extern __shared__ float bsm[];
    float* sRel = bsm;                  // 125 * 100
    float* sQ   = bsm + 125 * RSTRIDE;  // 128 * 96
    int head = blockIdx.y;
    int qb = blockIdx.x * 128;
    int tid = threadIdx.x;
    const float* qp = g_pool + head * NTOK * HD_;

    if (blockIdx.x == 0 && tid < BROW)
        g_bias[(head * NTOK) * BROW + tid] = 0.f;   // cls query row

    for (int idx = tid; idx < 125 * 24; idx += 256) {
        int row = idx / 24, c4 = idx - row * 24;
        const float* src = row < 15 ? rel_t + row * 96
                         : row < 70 ? rel_h + (row - 15) * 96
                                    : rel_w + (row - 70) * 96;
        float4 v = *(const float4*)(src + c4 * 4);
        float* dst = sRel + row * RSTRIDE + c4 * 4;
        dst[0] = v.x * LOG2E; dst[1] = v.y * LOG2E;
        dst[2] = v.z * LOG2E; dst[3] = v.w * LOG2E;
    }
    for (int idx = tid; idx < 128 * 24; idx += 256) {
        int r = idx / 24, c4 = idx - r * 24;
        *(float4*)(sQ + r * 96 + c4 * 4) =
            *(const float4*)(qp + (qb + 1 + r) * 96 + c4 * 4);
    }
    __syncthreads();

    for (int it = tid; it < 128 * 64; it += 256) {
        int ql = it >> 6, i = it & 63;
        int s = qb + ql;
        int t = s / 784; int rr = s - t * 784;
        int h = rr / 28; int w = rr - h * 28;
        int row = (i < 8)  ? (t - i + 7)
                : (i < 36) ? 15 + (h - (i - 8) + 27)
                           : 70 + (w - (i - 36) + 27);
        const float* q4 = sQ + ql * 96;
        const float* r4 = sRel + row * RSTRIDE;
        float sum = 0.f;
        #pragma unroll
        for (int c = 0; c < 96; c += 4) {
            float4 a = *(const float4*)(q4 + c);
            float4 b = *(const float4*)(r4 + c);
            sum += a.x*b.x + a.y*b.y + a.z*b.z + a.w*b.w;
        }
        g_bias[(head * NTOK + s + 1) * BROW + i] = sum;
    }
    // pad cols 64..67
    for (int idx = tid; idx < 128 * 4; idx += 256) {
        int ql = idx >> 2, i = 64 + (idx & 3);
        g_bias[(head * NTOK + qb + 1 + ql) * BROW + i] = 0.f;
    }
}

// ---------------------------------------------------------------------------
// Flash attention, bf16 mma m16n8k16: Mq=96 x Nk=64, 12 warps.
// grid (66, 2), block 384, dyn smem 83200 B.
// ---------------------------------------------------------------------------
#define SQ_OFF  0        // 6 mt * 6 kt * 32 * 4 = 4608 words (bf16x2)
#define SK_OFF  4608     // 8 nt * 6 kt * 32 * 2 = 3072
#define SV_OFF  7680     // 12 nt * 4 kt * 32 * 2 = 3072
#define SP_OFF  10752    // 6 mt * 4 kt * 32 * 4 = 3072
#define SB_OFF  13824    // 96 * 68 = 6528 (fp32)
#define SRM_OFF 20352    // 2 * 96
#define SRS_OFF 20544    // 2 * 96
#define SKI_OFF 20736    // 64
#define FLASH_SMEM (20800 * 4)

__global__ __launch_bounds__(384, 1) void flash_mma_kernel()
{
    extern __shared__ float sm[];
    float* sQp = sm + SQ_OFF;
    float* sKp = sm + SK_OFF;
    float* sVp = sm + SV_OFF;
    __nv_bfloat16* sVh = (__nv_bfloat16*)sVp;
    float* sPp = sm + SP_OFF;
    float* sB  = sm + SB_OFF;
    float* sRM = sm + SRM_OFF;
    float* sRS = sm + SRS_OFF;
    int*   sKI = (int*)(sm + SKI_OFF);

    const int head = blockIdx.y;
    const int q0 = blockIdx.x * 96;
    const int tid = threadIdx.x;
    const int lane = tid & 31, warp = tid >> 5;
    const int mw = warp >> 1, nw = warp & 1;

    const float* qp = g_pool + head * NTOK * HD_;
    const float* kp = g_pool + (2 + head) * NTOK * HD_;
    const float* vp = g_pool + (4 + head) * NTOK * HD_;

    // Load Q into bf16 A-fragment-permuted layout
    {
        int r_g = tid >> 2;
        int row = q0 + r_g;
        bool ok = row < NTOK;
        int mt = r_g >> 4, r = r_g & 15;
        #pragma unroll
        for (int c4 = tid & 3; c4 < 24; c4 += 4) {
            float4 v = ok ? *(const float4*)(qp + row * 96 + c4 * 4)
                          : make_float4(0.f, 0.f, 0.f, 0.f);
            int p0 = 2 * c4;
            int kt = p0 >> 3, p = p0 & 7;
            unsigned* dst = (unsigned*)sQp + (mt * 6 + kt) * 128;
            int rh = (r >> 3) & 1;
            dst[((r & 7) * 4 + (p & 3)) * 4 + rh + 2 * (p >> 2)]       = pack_bf16(v.x, v.y);
            int p1 = p + 1;
            dst[((r & 7) * 4 + (p1 & 3)) * 4 + rh + 2 * (p1 >> 2)]     = pack_bf16(v.z, v.w);
        }
    }
    // Stage bias rows for this block's 96 queries
    for (int idx = tid; idx < 96 * 17; idx += 384) {
        int r = idx / 17, c4 = idx - r * 17;
        int row = q0 + r; if (row >= NTOK) row = NTOK - 1;
        *(float4*)(sB + r * 68 + c4 * 4) =
            *(const float4*)(g_bias + (head * NTOK + row) * BROW + c4 * 4);
    }

    float mA = -1e30f, mB = -1e30f, lA = 0.f, lB = 0.f;
    float oacc[6][4] = {};
    const int rloc = mw * 16 + (lane >> 2);
    const float* Br0 = sB + rloc * 68;
    const float* Br1 = Br0 + 8 * 68;

    for (int k0 = 0; k0 < NTOK; k0 += 64) {
        __syncthreads();
        // Load K (B-frag layout) and V (B-frag layout, scalar bf16 stores)
        {
            int r = tid & 63;
            int rowg = k0 + r;
            bool ok = rowg < NTOK;
            int ntk = r >> 3, gnk = r & 7;
            int ktv = r >> 4, pv = (r & 15) >> 1, ev = r & 1;
            #pragma unroll
            for (int c4 = tid >> 6; c4 < 24; c4 += 6) {
                float4 kv = ok ? *(const float4*)(kp + rowg * 96 + c4 * 4)
                               : make_float4(0.f, 0.f, 0.f, 0.f);
                int p0 = 2 * c4;
                int kt = p0 >> 3, p = p0 & 7;
                unsigned* dK = (unsigned*)sKp + (ntk * 6 + kt) * 64;
                dK[(gnk * 4 + (p & 3)) * 2 + (p >> 2)]           = pack_bf16(kv.x, kv.y);
                int p1 = p + 1;
                dK[(gnk * 4 + (p1 & 3)) * 2 + (p1 >> 2)]         = pack_bf16(kv.z, kv.w);

                float4 vv = ok ? *(const float4*)(vp + rowg * 96 + c4 * 4)
                               : make_float4(0.f, 0.f, 0.f, 0.f);
                float va[4] = {vv.x, vv.y, vv.z, vv.w};
                #pragma unroll
                for (int j = 0; j < 4; j++) {
                    int c = c4 * 4 + j;
                    int ntv = c >> 3, gnv = c & 7;
                    int hidx = ((((ntv * 4 + ktv) * 32 + gnv * 4 + (pv & 3)) * 2 + (pv >> 2)) * 2 + ev);
                    sVh[hidx] = __float2bfloat16_rn(va[j]);
                }
            }
        }
        if (tid < 64) {
            int kg = k0 + tid;
            int packed;
            if (kg >= NTOK) packed = -1;
            else if (kg == 0) packed = 64 | (65 << 8) | (66 << 16);
            else {
                int ss = kg - 1;
                int t = ss / 784; int rr2 = ss - t * 784;
                int hh = rr2 / 28; int ww = rr2 - hh * 28;
                packed = t | ((8 + hh) << 8) | ((36 + ww) << 16);
            }
            sKI[tid] = packed;
        }
        __syncthreads();

        // S = Q K^T  (bf16 mma)
        float d[4][4] = {};
        #pragma unroll
        for (int kt = 0; kt < 6; kt++) {
            float4 a = *(const float4*)(sQp + ((mw * 6 + kt) * 32 + lane) * 4);
            #pragma unroll
            for (int nt = 0; nt < 4; nt++) {
                float2 b = *(const float2*)(sKp + (((nw * 4 + nt) * 6 + kt) * 32 + lane) * 2);
                mma16(d[nt], a, b);
            }
        }

        // scale + bias + mask, track row max
        float rm0 = -1e30f, rm1 = -1e30f;
        #pragma unroll
        for (int nt = 0; nt < 4; nt++) {
            int c0 = nw * 32 + nt * 8 + (lane & 3) * 2;
            int p0 = sKI[c0], p1 = sKI[c0 + 1];
            if (p0 >= 0) {
                int i0 = p0 & 255, i1 = (p0 >> 8) & 255, i2 = p0 >> 16;
                d[nt][0] = d[nt][0] * SCL2 + (Br0[i0] + Br0[i1] + Br0[i2]);
                d[nt][2] = d[nt][2] * SCL2 + (Br1[i0] + Br1[i1] + Br1[i2]);
            } else { d[nt][0] = -1e30f; d[nt][2] = -1e30f; }
            if (p1 >= 0) {
                int i0 = p1 & 255, i1 = (p1 >> 8) & 255, i2 = p1 >> 16;
                d[nt][1] = d[nt][1] * SCL2 + (Br0[i0] + Br0[i1] + Br0[i2]);
                d[nt][3] = d[nt][3] * SCL2 + (Br1[i0] + Br1[i1] + Br1[i2]);
            } else { d[nt][1] = -1e30f; d[nt][3] = -1e30f; }
            rm0 = fmaxf(rm0, fmaxf(d[nt][0], d[nt][1]));
            rm1 = fmaxf(rm1, fmaxf(d[nt][2], d[nt][3]));
        }
        rm0 = fmaxf(rm0, __shfl_xor_sync(0xffffffffu, rm0, 1));
        rm0 = fmaxf(rm0, __shfl_xor_sync(0xffffffffu, rm0, 2));
        rm1 = fmaxf(rm1, __shfl_xor_sync(0xffffffffu, rm1, 1));
        rm1 = fmaxf(rm1, __shfl_xor_sync(0xffffffffu, rm1, 2));
        if ((lane & 3) == 0) {
            sRM[nw * 96 + rloc]     = rm0;
            sRM[nw * 96 + rloc + 8] = rm1;
        }
        __syncthreads();
        rm0 = fmaxf(rm0, sRM[(1 - nw) * 96 + rloc]);
        rm1 = fmaxf(rm1, sRM[(1 - nw) * 96 + rloc + 8]);
        float nm0 = fmaxf(mA, rm0), nm1 = fmaxf(mB, rm1);
        float cf0 = fexp2(mA - nm0), cf1 = fexp2(mB - nm1);
        mA = nm0; mB = nm1;

        float s0 = 0.f, s1 = 0.f;
        #pragma unroll
        for (int nt = 0; nt < 4; nt++) {
            float p00 = fexp2(d[nt][0] - nm0), p01 = fexp2(d[nt][1] - nm0);
            float p10 = fexp2(d[nt][2] - nm1), p11 = fexp2(d[nt][3] - nm1);
            s0 += p00 + p01; s1 += p10 + p11;
            int ktp = mw * 4 + nw * 2 + (nt >> 1);
            unsigned* dp = (unsigned*)sPp + (ktp * 32 + lane) * 4 + 2 * (nt & 1);
            dp[0] = pack_bf16(p00, p01);
            dp[1] = pack_bf16(p10, p11);
        }
        s0 += __shfl_xor_sync(0xffffffffu, s0, 1);
        s0 += __shfl_xor_sync(0xffffffffu, s0, 2);
        s1 += __shfl_xor_sync(0xffffffffu, s1, 1);
        s1 += __shfl_xor_sync(0xffffffffu, s1, 2);
        if ((lane & 3) == 0) {
            sRS[nw * 96 + rloc]     = s0;
            sRS[nw * 96 + rloc + 8] = s1;
        }
        __syncthreads();
        lA = lA * cf0 + s0 + sRS[(1 - nw) * 96 + rloc];
        lB = lB * cf1 + s1 + sRS[(1 - nw) * 96 + rloc + 8];
        #pragma unroll
        for (int nt = 0; nt < 6; nt++) {
            oacc[nt][0] *= cf0; oacc[nt][1] *= cf0;
            oacc[nt][2] *= cf1; oacc[nt][3] *= cf1;
        }
        // O += P V (bf16 mma)
        #pragma unroll
        for (int kt = 0; kt < 4; kt++) {
            float4 a = *(const float4*)(sPp + ((mw * 4 + kt) * 32 + lane) * 4);
            #pragma unroll
            for (int nt = 0; nt < 6; nt++) {
                float2 b = *(const float2*)(sVp + (((nw * 6 + nt) * 4 + kt) * 32 + lane) * 2);
                mma16(oacc[nt], a, b);
            }
        }
    }

    // epilogue: normalize, residual, store
    int r0 = q0 + mw * 16 + (lane >> 2);
    int r1 = r0 + 8;
    float il0 = 1.f / lA, il1 = 1.f / lB;
    #pragma unroll
    for (int nt = 0; nt < 6; nt++) {
        int c = nw * 48 + nt * 8 + (lane & 3) * 2;
        if (r0 < NTOK) {
            float e0 = (r0 >= 1) ? qp[r0 * 96 + c]     : 0.f;
            float e1 = (r0 >= 1) ? qp[r0 * 96 + c + 1] : 0.f;
            g_att[r0 * 192 + head * 96 + c]     = oacc[nt][0] * il0 + e0;
            g_att[r0 * 192 + head * 96 + c + 1] = oacc[nt][1] * il0 + e1;
        }
        if (r1 < NTOK) {
            g_att[r1 * 192 + head * 96 + c]     = oacc[nt][2] * il1 + qp[r1 * 96 + c];
            g_att[r1 * 192 + head * 96 + c + 1] = oacc[nt][3] * il1 + qp[r1 * 96 + c + 1];
        }
    }
}

// ---------------------------------------------------------------------------
extern "C" void kernel_launch(void* const* d_in, const int* in_sizes, int n_in,
                              void* d_out, int out_size)
{
    const float* x      = (const float*)d_in[0];
    const float* qkv_w  = (const float*)d_in[1];
    const float* qkv_b  = (const float*)d_in[2];
    const float* proj_w = (const float*)d_in[3];
    const float* proj_b = (const float*)d_in[4];
    const float* pqw    = (const float*)d_in[5];
    const float* pkw    = (const float*)d_in[6];
    const float* pvw    = (const float*)d_in[7];
    const float* nqg    = (const float*)d_in[8];
    const float* nqb    = (const float*)d_in[9];
    const float* nkg    = (const float*)d_in[10];
    const float* nkb    = (const float*)d_in[11];
    const float* nvg    = (const float*)d_in[12];
    const float* nvb    = (const float*)d_in[13];
    const float* rel_h  = (const float*)d_in[14];
    const float* rel_w  = (const float*)d_in[15];
    const float* rel_t  = (const float*)d_in[16];
    float* out = (float*)d_out;

    const int smem_bias = (125 * RSTRIDE + 128 * 96) * 4;
    cudaFuncSetAttribute(flash_mma_kernel, cudaFuncAttributeMaxDynamicSharedMemorySize, FLASH_SMEM);
    cudaFuncSetAttribute(bias_kernel, cudaFuncAttributeMaxDynamicSharedMemorySize, smem_bias);

    dim3 g1(99, 9);
    gemm_mma_kernel<<<g1, 256>>>(x, qkv_w, qkv_b, nullptr, NTOK, 576, 0);

    dim3 g2(NTOK, 6);
    pool_kernel<<<g2, 96>>>(pqw, pkw, pvw, nqg, nqb, nkg, nkb, nvg, nvb);

    dim3 g3(49, 2);
    bias_kernel<<<g3, 256, smem_bias>>>(rel_h, rel_w, rel_t);

    dim3 g4(66, 2);
    flash_mma_kernel<<<g4, 384, FLASH_SMEM>>>();

    dim3 g5(99, 3);
    gemm_mma_kernel<<<g5, 256>>>(nullptr, proj_w, proj_b, out, NTOK, 192, 1);
}

// round 5
// speedup vs baseline: 3.6415x; 1.1495x over previous
#include <cuda_runtime.h>
#include <cuda_bf16.h>
#include <math.h>

#define T_    8
#define H_    28
#define W_    28
#define SP_   6272
#define NTOK  6273
#define DIM_  192
#define HD_   96
#define BROW  68
#define SCALE_ 0.1020620726159658f   // 96^-0.5
#define LOG2E  1.4426950408889634f
#define SCL2   (SCALE_ * LOG2E)

// Scratch (static device memory — no allocations)
__device__ float g_raw [6 * NTOK * HD_];
__device__ float g_pool[6 * NTOK * HD_];
__device__ float g_bias[2 * NTOK * BROW];
__device__ float g_att [NTOK * DIM_];

// ---------------------------------------------------------------------------
__device__ __forceinline__ float cvt_tf32(float x) {
    unsigned u; asm("cvt.rna.tf32.f32 %0, %1;" : "=r"(u) : "f"(x));
    return __uint_as_float(u);
}
__device__ __forceinline__ float fexp2(float x) {
    float y; asm("ex2.approx.ftz.f32 %0, %1;" : "=f"(y) : "f"(x)); return y;
}
__device__ __forceinline__ unsigned pack_bf16(float x, float y) {
    __nv_bfloat162 h = __float22bfloat162_rn(make_float2(x, y));
    return *(unsigned*)&h;
}
__device__ __forceinline__ void mma8(float* d, const float4& a, const float2& b) {
    asm volatile("mma.sync.aligned.m16n8k8.row.col.f32.tf32.tf32.f32 "
        "{%0,%1,%2,%3}, {%4,%5,%6,%7}, {%8,%9}, {%0,%1,%2,%3};"
        : "+f"(d[0]), "+f"(d[1]), "+f"(d[2]), "+f"(d[3])
        : "r"(__float_as_uint(a.x)), "r"(__float_as_uint(a.y)),
          "r"(__float_as_uint(a.z)), "r"(__float_as_uint(a.w)),
          "r"(__float_as_uint(b.x)), "r"(__float_as_uint(b.y)));
}
__device__ __forceinline__ void mma16(float* d, const float4& a, const float2& b) {
    asm volatile("mma.sync.aligned.m16n8k16.row.col.f32.bf16.bf16.f32 "
        "{%0,%1,%2,%3}, {%4,%5,%6,%7}, {%8,%9}, {%0,%1,%2,%3};"
        : "+f"(d[0]), "+f"(d[1]), "+f"(d[2]), "+f"(d[3])
        : "r"(__float_as_uint(a.x)), "r"(__float_as_uint(a.y)),
          "r"(__float_as_uint(a.z)), "r"(__float_as_uint(a.w)),
          "r"(__float_as_uint(b.x)), "r"(__float_as_uint(b.y)));
}

// ---------------------------------------------------------------------------
// tf32 mma GEMM: C[M x N] = A[M x 192] @ Bm[N x 192]^T + bias  (unchanged R4)
// ---------------------------------------------------------------------------
__global__ __launch_bounds__(256) void gemm_mma_kernel(
    const float* __restrict__ A, const float* __restrict__ Bm,
    const float* __restrict__ bias, float* __restrict__ out,
    int M, int N, int mode)
{
    __shared__ float sA[6144];
    __shared__ float sB[6144];
    const float* Ap = (mode == 1) ? g_att : A;

    int tid = threadIdx.x, lane = tid & 31, warp = tid >> 5;
    int mw = warp >> 1, nh = warp & 1;
    int m0 = blockIdx.x * 64, n0 = blockIdx.y * 64;

    float d[4][4] = {};

    for (int k0 = 0; k0 < 192; k0 += 96) {
        __syncthreads();
        {
            int r_g = tid >> 2, r = r_g & 15, mt = r_g >> 4;
            int row = m0 + r_g; if (row >= M) row = M - 1;
            #pragma unroll
            for (int c4 = tid & 3; c4 < 24; c4 += 4) {
                float4 v = *(const float4*)(Ap + row * 192 + k0 + c4 * 4);
                int base = (mt * 12 + (c4 >> 1)) * 128 + (r & 7) * 16
                           + ((r >> 3) & 1) + 2 * (c4 & 1);
                sA[base + 0]  = cvt_tf32(v.x); sA[base + 4]  = cvt_tf32(v.y);
                sA[base + 8]  = cvt_tf32(v.z); sA[base + 12] = cvt_tf32(v.w);
            }
        }
        {
            int r_g = tid >> 2;
            int nt = r_g >> 3, gn = r_g & 7;
            #pragma unroll
            for (int c4 = tid & 3; c4 < 24; c4 += 4) {
                float4 v = *(const float4*)(Bm + (n0 + r_g) * 192 + k0 + c4 * 4);
                int base = (nt * 12 + (c4 >> 1)) * 64 + gn * 8 + (c4 & 1);
                sB[base + 0] = cvt_tf32(v.x); sB[base + 2] = cvt_tf32(v.y);
                sB[base + 4] = cvt_tf32(v.z); sB[base + 6] = cvt_tf32(v.w);
            }
        }
        __syncthreads();
        #pragma unroll
        for (int kt = 0; kt < 12; kt++) {
            float4 a = *(const float4*)(sA + ((mw * 12 + kt) * 32 + lane) * 4);
            #pragma unroll
            for (int nt = 0; nt < 4; nt++) {
                float2 b = *(const float2*)(sB + (((nh * 4 + nt) * 12 + kt) * 32 + lane) * 2);
                mma8(d[nt], a, b);
            }
        }
    }

    int g = lane >> 2, tq = lane & 3;
    int r0 = m0 + mw * 16 + g, r1 = r0 + 8;
    #pragma unroll
    for (int nt = 0; nt < 4; nt++) {
        int col = n0 + nh * 32 + nt * 8 + tq * 2;
        #pragma unroll
        for (int e = 0; e < 2; e++) {
            int c = col + e;
            float b = bias[c];
            float v0 = d[nt][e]     + b;
            float v1 = d[nt][e + 2] + b;
            if (mode == 0) {
                int which = c / DIM_;
                int rem   = c - which * DIM_;
                int head  = rem / HD_;
                int cc    = rem - head * HD_;
                int base  = (which * 2 + head) * NTOK * HD_ + cc;
                if (r0 < M) g_raw[base + r0 * HD_] = v0;
                if (r1 < M) g_raw[base + r1 * HD_] = v1;
            } else {
                if (r0 < M) out[r0 * N + c] = v0;
                if (r1 < M) out[r1 * N + c] = v1;
            }
        }
    }
}

// ---------------------------------------------------------------------------
// Attention pool: 1 warp per token, weights staged in smem, shuffle-only LN.
// grid: (785, 6)  block: 256
// ---------------------------------------------------------------------------
__global__ __launch_bounds__(256) void pool_kernel(
    const float* __restrict__ wq, const float* __restrict__ wk, const float* __restrict__ wv,
    const float* __restrict__ gq, const float* __restrict__ bq,
    const float* __restrict__ gk, const float* __restrict__ bk,
    const float* __restrict__ gv, const float* __restrict__ bv)
{
    __shared__ float sW[27 * 96];
    int tid = threadIdx.x;
    int yy  = blockIdx.y;
    int tensor = yy >> 1, head = yy & 1;

    const float* wc = (tensor == 0) ? wq : (tensor == 1) ? wk : wv;
    const float* g  = (tensor == 0) ? gq : (tensor == 1) ? gk : gv;
    const float* b  = (tensor == 0) ? bq : (tensor == 1) ? bk : bv;

    for (int i = tid; i < 27 * 96; i += 256) {
        int tap = i / 96, c = i - tap * 96;
        sW[i] = wc[c * 27 + tap];
    }
    __syncthreads();

    int w = tid >> 5, lane = tid & 31;
    int tok = blockIdx.x * 8 + w;
    if (tok < NTOK) {
        const float* in = g_raw + (tensor * 2 + head) * NTOK * HD_;
        float v0, v1, v2;
        if (tok == 0) {
            v0 = in[lane]; v1 = in[lane + 32]; v2 = in[lane + 64];
        } else {
            int s = tok - 1;
            int t = s / 784; int r = s - t * 784;
            int h = r / 28;  int ww = r - h * 28;
            v0 = v1 = v2 = 0.f;
            #pragma unroll
            for (int dt = -1; dt <= 1; dt++) {
                int tt = t + dt; if ((unsigned)tt >= (unsigned)T_) continue;
                #pragma unroll
                for (int dh = -1; dh <= 1; dh++) {
                    int hh = h + dh; if ((unsigned)hh >= (unsigned)H_) continue;
                    #pragma unroll
                    for (int dw = -1; dw <= 1; dw++) {
                        int w2 = ww + dw; if ((unsigned)w2 >= (unsigned)W_) continue;
                        int nb = 1 + (tt * 28 + hh) * 28 + w2;
                        int tap = (dt + 1) * 9 + (dh + 1) * 3 + (dw + 1);
                        const float* p  = in + nb * 96;
                        const float* wr = sW + tap * 96;
                        v0 += p[lane]      * wr[lane];
                        v1 += p[lane + 32] * wr[lane + 32];
                        v2 += p[lane + 64] * wr[lane + 64];
                    }
                }
            }
        }
        float s1 = v0 + v1 + v2;
        float s2 = v0 * v0 + v1 * v1 + v2 * v2;
        #pragma unroll
        for (int o = 1; o < 32; o <<= 1) {
            s1 += __shfl_xor_sync(0xffffffffu, s1, o);
            s2 += __shfl_xor_sync(0xffffffffu, s2, o);
        }
        float mean = s1 * (1.f / 96.f);
        float var  = s2 * (1.f / 96.f) - mean * mean;
        float is   = rsqrtf(var + 1e-5f);
        float* outp = g_pool + (tensor * 2 + head) * NTOK * HD_ + tok * 96;
        outp[lane]      = (v0 - mean) * is * g[lane]      + b[lane];
        outp[lane + 32] = (v1 - mean) * is * g[lane + 32] + b[lane + 32];
        outp[lane + 64] = (v2 - mean) * is * g[lane + 64] + b[lane + 64];
    }
}

// ---------------------------------------------------------------------------
// Rel-bias precompute (unchanged R4)
#define RSTRIDE 100
__global__ __launch_bounds__(256) void bias_kernel(
    const float* __restrict__ rel_h, const float* __restrict__ rel_w,
    const float* __restrict__ rel_t)
{
    extern __shared__ float bsm[];
    float* sRel = bsm;
    float* sQ   = bsm + 125 * RSTRIDE;
    int head = blockIdx.y;
    int qb = blockIdx.x * 128;
    int tid = threadIdx.x;
    const float* qp = g_pool + head * NTOK * HD_;

    if (blockIdx.x == 0 && tid < BROW)
        g_bias[(head * NTOK) * BROW + tid] = 0.f;

    for (int idx = tid; idx < 125 * 24; idx += 256) {
        int row = idx / 24, c4 = idx - row * 24;
        const float* src = row < 15 ? rel_t + row * 96
                         : row < 70 ? rel_h + (row - 15) * 96
                                    : rel_w + (row - 70) * 96;
        float4 v = *(const float4*)(src + c4 * 4);
        float* dst = sRel + row * RSTRIDE + c4 * 4;
        dst[0] = v.x * LOG2E; dst[1] = v.y * LOG2E;
        dst[2] = v.z * LOG2E; dst[3] = v.w * LOG2E;
    }
    for (int idx = tid; idx < 128 * 24; idx += 256) {
        int r = idx / 24, c4 = idx - r * 24;
        *(float4*)(sQ + r * 96 + c4 * 4) =
            *(const float4*)(qp + (qb + 1 + r) * 96 + c4 * 4);
    }
    __syncthreads();

    for (int it = tid; it < 128 * 64; it += 256) {
        int ql = it >> 6, i = it & 63;
        int s = qb + ql;
        int t = s / 784; int rr = s - t * 784;
        int h = rr / 28; int w = rr - h * 28;
        int row = (i < 8)  ? (t - i + 7)
                : (i < 36) ? 15 + (h - (i - 8) + 27)
                           : 70 + (w - (i - 36) + 27);
        const float* q4 = sQ + ql * 96;
        const float* r4 = sRel + row * RSTRIDE;
        float sum = 0.f;
        #pragma unroll
        for (int c = 0; c < 96; c += 4) {
            float4 a = *(const float4*)(q4 + c);
            float4 b = *(const float4*)(r4 + c);
            sum += a.x*b.x + a.y*b.y + a.z*b.z + a.w*b.w;
        }
        g_bias[(head * NTOK + s + 1) * BROW + i] = sum;
    }
    for (int idx = tid; idx < 128 * 4; idx += 256) {
        int ql = idx >> 2, i = 64 + (idx & 3);
        g_bias[(head * NTOK + qb + 1 + ql) * BROW + i] = 0.f;
    }
}

// ---------------------------------------------------------------------------
// Flash attention v2: split-KV warp halves, register P, double-buffered K/V.
// grid (66, 2), block 384 (12 warps: 6 m-tiles x 2 key-halves).
// ---------------------------------------------------------------------------
#define SQ_OFF  0        // 6 mt * 6 kt * 128 = 4608 words
#define SK_OFF  4608     // 2 buf * 3072
#define SV_OFF  10752    // 2 buf * 3072
#define SB_OFF  16896    // 96 * 68 = 6528
#define SKI_OFF 23424    // 2 buf * 64 ints
#define FLASH_SMEM (23552 * 4)
#define NT_TILES 99      // ceil(6273/64)
#define OSTR 100

__device__ __forceinline__ void stage_kv(
    float* sm, const float* kp, const float* vp, int k0n, int bufn, int tid)
{
    float* sKb = sm + SK_OFF + bufn * 3072;
    __nv_bfloat16* sVhb = (__nv_bfloat16*)(sm + SV_OFF + bufn * 3072);
    int* sKIb = (int*)(sm + SKI_OFF) + bufn * 64;

    int r = tid & 63;
    int rowg = k0n + r;
    bool ok = rowg < NTOK;
    int ntk = r >> 3, gnk = r & 7;
    int ktv = r >> 4, pv = (r & 15) >> 1, ev = r & 1;
    #pragma unroll
    for (int c4 = tid >> 6; c4 < 24; c4 += 6) {
        float4 kv = ok ? *(const float4*)(kp + rowg * 96 + c4 * 4)
                       : make_float4(0.f, 0.f, 0.f, 0.f);
        int p0 = 2 * c4;
        int kt = p0 >> 3, p = p0 & 7;
        unsigned* dK = (unsigned*)sKb + (ntk * 6 + kt) * 64;
        dK[(gnk * 4 + (p & 3)) * 2 + (p >> 2)]   = pack_bf16(kv.x, kv.y);
        int p1 = p + 1;
        dK[(gnk * 4 + (p1 & 3)) * 2 + (p1 >> 2)] = pack_bf16(kv.z, kv.w);

        float4 vv = ok ? *(const float4*)(vp + rowg * 96 + c4 * 4)
                       : make_float4(0.f, 0.f, 0.f, 0.f);
        float va[4] = {vv.x, vv.y, vv.z, vv.w};
        #pragma unroll
        for (int j = 0; j < 4; j++) {
            int c = c4 * 4 + j;
            int ntv = c >> 3, gnv = c & 7;
            int hidx = ((((ntv * 4 + ktv) * 32 + gnv * 4 + (pv & 3)) * 2 + (pv >> 2)) * 2 + ev);
            sVhb[hidx] = __float2bfloat16_rn(va[j]);
        }
    }
    if (tid < 64) {
        int kg = k0n + tid;
        int packed;
        if (kg >= NTOK) packed = -1;
        else if (kg == 0) packed = 64 | (65 << 8) | (66 << 16);
        else {
            int ss = kg - 1;
            int t = ss / 784; int rr2 = ss - t * 784;
            int hh = rr2 / 28; int ww = rr2 - hh * 28;
            packed = t | ((8 + hh) << 8) | ((36 + ww) << 16);
        }
        sKIb[tid] = packed;
    }
}

__global__ __launch_bounds__(384, 1) void flash_mma_kernel()
{
    extern __shared__ float sm[];
    float* sQp = sm + SQ_OFF;
    float* sB  = sm + SB_OFF;

    const int head = blockIdx.y;
    const int q0 = blockIdx.x * 96;
    const int tid = threadIdx.x;
    const int lane = tid & 31, warp = tid >> 5;
    const int mw = warp >> 1, nw = warp & 1;

    const float* qp = g_pool + head * NTOK * HD_;
    const float* kp = g_pool + (2 + head) * NTOK * HD_;
    const float* vp = g_pool + (4 + head) * NTOK * HD_;

    // Q -> bf16 A-fragment layout
    {
        int r_g = tid >> 2;
        int row = q0 + r_g;
        bool ok = row < NTOK;
        int mt = r_g >> 4, r = r_g & 15;
        #pragma unroll
        for (int c4 = tid & 3; c4 < 24; c4 += 4) {
            float4 v = ok ? *(const float4*)(qp + row * 96 + c4 * 4)
                          : make_float4(0.f, 0.f, 0.f, 0.f);
            int p0 = 2 * c4;
            int kt = p0 >> 3, p = p0 & 7;
            unsigned* dst = (unsigned*)sQp + (mt * 6 + kt) * 128;
            int rh = (r >> 3) & 1;
            dst[((r & 7) * 4 + (p & 3)) * 4 + rh + 2 * (p >> 2)]   = pack_bf16(v.x, v.y);
            int p1 = p + 1;
            dst[((r & 7) * 4 + (p1 & 3)) * 4 + rh + 2 * (p1 >> 2)] = pack_bf16(v.z, v.w);
        }
    }
    // bias rows
    for (int idx = tid; idx < 96 * 17; idx += 384) {
        int r = idx / 17, c4 = idx - r * 17;
        int row = q0 + r; if (row >= NTOK) row = NTOK - 1;
        *(float4*)(sB + r * 68 + c4 * 4) =
            *(const float4*)(g_bias + (head * NTOK + row) * BROW + c4 * 4);
    }
    // prologue stage tile 0
    stage_kv(sm, kp, vp, 0, 0, tid);

    float mA = -1e30f, mB = -1e30f, lA = 0.f, lB = 0.f;
    float oacc[12][4] = {};
    const int rloc = mw * 16 + (lane >> 2);
    const float* Br0 = sB + rloc * 68;
    const float* Br1 = Br0 + 8 * 68;

    for (int t = 0; t < NT_TILES; t++) {
        int buf = t & 1;
        __syncthreads();
        if (t + 1 < NT_TILES) stage_kv(sm, kp, vp, (t + 1) * 64, buf ^ 1, tid);

        float* sKb = sm + SK_OFF + buf * 3072;
        float* sVb = sm + SV_OFF + buf * 3072;
        int*   sKIb = (int*)(sm + SKI_OFF) + buf * 64;

        // S = Q K^T over this warp's key half
        float d[4][4] = {};
        #pragma unroll
        for (int kt = 0; kt < 6; kt++) {
            float4 a = *(const float4*)(sQp + ((mw * 6 + kt) * 32 + lane) * 4);
            #pragma unroll
            for (int nt = 0; nt < 4; nt++) {
                float2 b = *(const float2*)(sKb + (((nw * 4 + nt) * 6 + kt) * 32 + lane) * 2);
                mma16(d[nt], a, b);
            }
        }

        // scale + bias + mask, row max within warp only
        float rm0 = -1e30f, rm1 = -1e30f;
        #pragma unroll
        for (int nt = 0; nt < 4; nt++) {
            int c0 = nw * 32 + nt * 8 + (lane & 3) * 2;
            int p0 = sKIb[c0], p1 = sKIb[c0 + 1];
            if (p0 >= 0) {
                int i0 = p0 & 255, i1 = (p0 >> 8) & 255, i2 = p0 >> 16;
                d[nt][0] = d[nt][0] * SCL2 + (Br0[i0] + Br0[i1] + Br0[i2]);
                d[nt][2] = d[nt][2] * SCL2 + (Br1[i0] + Br1[i1] + Br1[i2]);
            } else { d[nt][0] = -1e30f; d[nt][2] = -1e30f; }
            if (p1 >= 0) {
                int i0 = p1 & 255, i1 = (p1 >> 8) & 255, i2 = p1 >> 16;
                d[nt][1] = d[nt][1] * SCL2 + (Br0[i0] + Br0[i1] + Br0[i2]);
                d[nt][3] = d[nt][3] * SCL2 + (Br1[i0] + Br1[i1] + Br1[i2]);
            } else { d[nt][1] = -1e30f; d[nt][3] = -1e30f; }
            rm0 = fmaxf(rm0, fmaxf(d[nt][0], d[nt][1]));
            rm1 = fmaxf(rm1, fmaxf(d[nt][2], d[nt][3]));
        }
        rm0 = fmaxf(rm0, __shfl_xor_sync(0xffffffffu, rm0, 1));
        rm0 = fmaxf(rm0, __shfl_xor_sync(0xffffffffu, rm0, 2));
        rm1 = fmaxf(rm1, __shfl_xor_sync(0xffffffffu, rm1, 1));
        rm1 = fmaxf(rm1, __shfl_xor_sync(0xffffffffu, rm1, 2));

        float nm0 = fmaxf(mA, rm0), nm1 = fmaxf(mB, rm1);
        float cf0 = fexp2(mA - nm0), cf1 = fexp2(mB - nm1);
        mA = nm0; mB = nm1;

        float s0 = 0.f, s1 = 0.f;
        unsigned pk[2][4];
        #pragma unroll
        for (int nt = 0; nt < 4; nt++) {
            float p00 = fexp2(d[nt][0] - nm0), p01 = fexp2(d[nt][1] - nm0);
            float p10 = fexp2(d[nt][2] - nm1), p11 = fexp2(d[nt][3] - nm1);
            s0 += p00 + p01; s1 += p10 + p11;
            pk[nt >> 1][(nt & 1) * 2 + 0] = pack_bf16(p00, p01);
            pk[nt >> 1][(nt & 1) * 2 + 1] = pack_bf16(p10, p11);
        }
        s0 += __shfl_xor_sync(0xffffffffu, s0, 1);
        s0 += __shfl_xor_sync(0xffffffffu, s0, 2);
        s1 += __shfl_xor_sync(0xffffffffu, s1, 1);
        s1 += __shfl_xor_sync(0xffffffffu, s1, 2);
        lA = lA * cf0 + s0;
        lB = lB * cf1 + s1;
        #pragma unroll
        for (int nt = 0; nt < 12; nt++) {
            oacc[nt][0] *= cf0; oacc[nt][1] *= cf0;
            oacc[nt][2] *= cf1; oacc[nt][3] *= cf1;
        }

        // O += P V   (P register-resident; k16 chunks of this warp's half)
        #pragma unroll
        for (int ktl = 0; ktl < 2; ktl++) {
            float4 af = make_float4(__uint_as_float(pk[ktl][0]), __uint_as_float(pk[ktl][1]),
                                    __uint_as_float(pk[ktl][2]), __uint_as_float(pk[ktl][3]));
            #pragma unroll
            for (int nt = 0; nt < 12; nt++) {
                float2 b = *(const float2*)(sVb + ((nt * 4 + nw * 2 + ktl) * 32 + lane) * 2);
                mma16(oacc[nt], af, b);
            }
        }
    }

    // split-KV combine across nw halves
    __syncthreads();
    float* sO  = sm;                // 96 * OSTR
    float* sMm = sm + 96 * OSTR;    // 96
    float* sLl = sMm + 96;          // 96
    int g = lane >> 2, tq = lane & 3;
    int rl0 = mw * 16 + g, rl1 = rl0 + 8;

    if (nw == 1) {
        #pragma unroll
        for (int nt = 0; nt < 12; nt++) {
            *(float2*)(sO + rl0 * OSTR + nt * 8 + tq * 2) = make_float2(oacc[nt][0], oacc[nt][1]);
            *(float2*)(sO + rl1 * OSTR + nt * 8 + tq * 2) = make_float2(oacc[nt][2], oacc[nt][3]);
        }
        if (tq == 0) {
            sMm[rl0] = mA; sMm[rl1] = mB;
            sLl[rl0] = lA; sLl[rl1] = lB;
        }
    }
    __syncthreads();
    if (nw == 0) {
        float m1a = sMm[rl0], l1a = sLl[rl0];
        float ma = fmaxf(mA, m1a);
        float a0 = fexp2(mA - ma), a1 = fexp2(m1a - ma);
        float inv0 = 1.f / (lA * a0 + l1a * a1);
        float m1b = sMm[rl1], l1b = sLl[rl1];
        float mb = fmaxf(mB, m1b);
        float b0 = fexp2(mB - mb), b1 = fexp2(m1b - mb);
        float inv1 = 1.f / (lB * b0 + l1b * b1);
        int r0 = q0 + rl0, r1 = q0 + rl1;
        #pragma unroll
        for (int nt = 0; nt < 12; nt++) {
            int c = nt * 8 + tq * 2;
            if (r0 < NTOK) {
                float2 o1 = *(float2*)(sO + rl0 * OSTR + c);
                float x0 = (oacc[nt][0] * a0 + o1.x * a1) * inv0;
                float x1 = (oacc[nt][1] * a0 + o1.y * a1) * inv0;
                if (r0 >= 1) { x0 += qp[r0 * 96 + c]; x1 += qp[r0 * 96 + c + 1]; }
                g_att[r0 * 192 + head * 96 + c]     = x0;
                g_att[r0 * 192 + head * 96 + c + 1] = x1;
            }
            if (r1 < NTOK) {
                float2 o1 = *(float2*)(sO + rl1 * OSTR + c);
                float x0 = (oacc[nt][2] * b0 + o1.x * b1) * inv1;
                float x1 = (oacc[nt][3] * b0 + o1.y * b1) * inv1;
                x0 += qp[r1 * 96 + c]; x1 += qp[r1 * 96 + c + 1];
                g_att[r1 * 192 + head * 96 + c]     = x0;
                g_att[r1 * 192 + head * 96 + c + 1] = x1;
            }
        }
    }
}

// ---------------------------------------------------------------------------
extern "C" void kernel_launch(void* const* d_in, const int* in_sizes, int n_in,
                              void* d_out, int out_size)
{
    const float* x      = (const float*)d_in[0];
    const float* qkv_w  = (const float*)d_in[1];
    const float* qkv_b  = (const float*)d_in[2];
    const float* proj_w = (const float*)d_in[3];
    const float* proj_b = (const float*)d_in[4];
    const float* pqw    = (const float*)d_in[5];
    const float* pkw    = (const float*)d_in[6];
    const float* pvw    = (const float*)d_in[7];
    const float* nqg    = (const float*)d_in[8];
    const float* nqb    = (const float*)d_in[9];
    const float* nkg    = (const float*)d_in[10];
    const float* nkb    = (const float*)d_in[11];
    const float* nvg    = (const float*)d_in[12];
    const float* nvb    = (const float*)d_in[13];
    const float* rel_h  = (const float*)d_in[14];
    const float* rel_w  = (const float*)d_in[15];
    const float* rel_t  = (const float*)d_in[16];
    float* out = (float*)d_out;

    const int smem_bias = (125 * RSTRIDE + 128 * 96) * 4;
    cudaFuncSetAttribute(flash_mma_kernel, cudaFuncAttributeMaxDynamicSharedMemorySize, FLASH_SMEM);
    cudaFuncSetAttribute(bias_kernel, cudaFuncAttributeMaxDynamicSharedMemorySize, smem_bias);

    dim3 g1(99, 9);
    gemm_mma_kernel<<<g1, 256>>>(x, qkv_w, qkv_b, nullptr, NTOK, 576, 0);

    dim3 g2(785, 6);
    pool_kernel<<<g2, 256>>>(pqw, pkw, pvw, nqg, nqb, nkg, nkb, nvg, nvb);

    dim3 g3(49, 2);
    bias_kernel<<<g3, 256, smem_bias>>>(rel_h, rel_w, rel_t);

    dim3 g4(66, 2);
    flash_mma_kernel<<<g4, 384, FLASH_SMEM>>>();

    dim3 g5(99, 3);
    gemm_mma_kernel<<<g5, 256>>>(nullptr, proj_w, proj_b, out, NTOK, 192, 1);
}